// round 2
// baseline (speedup 1.0000x reference)
#include <cuda_runtime.h>
#include <math.h>

// Triplet-margin ranking loss, GB300 sm_103a.
// anchor: (1, 2400) f32, positive: (P=5, 2400) f32, negative: (N=100000, 2400) f32
// loss = sum_{i<num_full} relu(d_ap[i % P] - d_an[i] + MARGIN)
// d_x = || anchor - x + EPS ||_2  (elementwise +EPS, torch pairwise_distance)

#define EPS    1e-6f
#define MARGIN 1.0f
#define DIM    2400
#define DIM4   (DIM / 4)   // 600 float4 per row

__device__ float g_dap[8];              // d_ap values (P <= 8; problem has P=5)
__device__ unsigned int g_counter;      // dynamic row ticket for loss_kernel

// ---------------------------------------------------------------------------
// Kernel 1: block b computes d_ap[b] (one positive row per block).
// Block 0 also zeroes the output scalar (poisoned 0xAA) and the row counter.
// ---------------------------------------------------------------------------
__global__ void __launch_bounds__(256)
dap_kernel(const float* __restrict__ anchor,
           const float* __restrict__ pos,
           float* __restrict__ out,
           int P)
{
    __shared__ float sred[8];
    const int b    = blockIdx.x;
    const int wid  = threadIdx.x >> 5;
    const int lane = threadIdx.x & 31;

    if (b == 0 && threadIdx.x == 0) {
        out[0]    = 0.0f;
        g_counter = 0u;
    }
    if (b >= P) return;

    const float4* a4 = reinterpret_cast<const float4*>(anchor);
    const float4* p4 = reinterpret_cast<const float4*>(pos + (size_t)b * DIM);
    float s = 0.0f;
    for (int k = threadIdx.x; k < DIM4; k += blockDim.x) {
        float4 a = a4[k];
        float4 p = p4[k];
        float d0 = a.x - p.x + EPS;
        float d1 = a.y - p.y + EPS;
        float d2 = a.z - p.z + EPS;
        float d3 = a.w - p.w + EPS;
        s = fmaf(d0, d0, s);
        s = fmaf(d1, d1, s);
        s = fmaf(d2, d2, s);
        s = fmaf(d3, d3, s);
    }
    #pragma unroll
    for (int o = 16; o > 0; o >>= 1)
        s += __shfl_xor_sync(0xFFFFFFFFu, s, o);
    if (lane == 0) sred[wid] = s;
    __syncthreads();
    if (threadIdx.x == 0) {
        float t = 0.0f;
        #pragma unroll
        for (int i = 0; i < 8; i++) t += sred[i];
        g_dap[b] = sqrtf(t);
    }
}

// ---------------------------------------------------------------------------
// Kernel 2: streaming over negative rows. Warp-per-row with DYNAMIC row
// assignment (atomic ticket) for perfect load balance. Anchor staged in
// shared (9.6 KB). One atomicAdd to the scalar per block.
// ---------------------------------------------------------------------------
__global__ void __launch_bounds__(256, 8)
loss_kernel(const float* __restrict__ anchor,
            const float* __restrict__ neg,
            float* __restrict__ out,
            int num_full, int P)
{
    __shared__ float4 sA[DIM4];        // anchor, 9600 B
    __shared__ float  sDap[8];
    __shared__ float  sWarp[8];

    const float4* a4 = reinterpret_cast<const float4*>(anchor);
    for (int k = threadIdx.x; k < DIM4; k += blockDim.x)
        sA[k] = a4[k];
    if (threadIdx.x < 8)
        sDap[threadIdx.x] = (threadIdx.x < P) ? g_dap[threadIdx.x] : 0.0f;
    __syncthreads();

    const int wid  = threadIdx.x >> 5;
    const int lane = threadIdx.x & 31;

    float acc = 0.0f;

    for (;;) {
        unsigned int row = 0u;
        if (lane == 0) row = atomicAdd(&g_counter, 1u);
        row = __shfl_sync(0xFFFFFFFFu, row, 0);
        if (row >= (unsigned int)num_full) break;

        const float4* n4 = reinterpret_cast<const float4*>(neg + (size_t)row * DIM);
        float s = 0.0f;
        // 600 float4 / 32 lanes = 18.75 iterations; unroll for MLP
        #pragma unroll 4
        for (int k = lane; k < DIM4; k += 32) {
            float4 a = sA[k];
            float4 n = __ldg(&n4[k]);
            float d0 = a.x - n.x + EPS;
            float d1 = a.y - n.y + EPS;
            float d2 = a.z - n.z + EPS;
            float d3 = a.w - n.w + EPS;
            s = fmaf(d0, d0, s);
            s = fmaf(d1, d1, s);
            s = fmaf(d2, d2, s);
            s = fmaf(d3, d3, s);
        }
        #pragma unroll
        for (int o = 16; o > 0; o >>= 1)
            s += __shfl_xor_sync(0xFFFFFFFFu, s, o);
        if (lane == 0) {
            float d_an = sqrtf(s);
            float t = sDap[row % (unsigned int)P] - d_an + MARGIN;
            acc += (t > 0.0f) ? t : 0.0f;
        }
    }

    // block reduction: lane 0 of each warp holds its partial
    if (lane == 0) sWarp[wid] = acc;
    __syncthreads();
    if (threadIdx.x == 0) {
        float bsum = 0.0f;
        #pragma unroll
        for (int i = 0; i < 8; i++) bsum += sWarp[i];
        atomicAdd(out, bsum);
    }
}

// ---------------------------------------------------------------------------
extern "C" void kernel_launch(void* const* d_in, const int* in_sizes, int n_in,
                              void* d_out, int out_size)
{
    const float* anchor = (const float*)d_in[0];
    const float* pos    = (const float*)d_in[1];
    const float* neg    = (const float*)d_in[2];
    float* out = (float*)d_out;

    const int P = in_sizes[1] / DIM;          // 5
    const int N = in_sizes[2] / DIM;          // 100000
    const int num_full = (N / P) * P;         // 100000

    dap_kernel<<<(P > 0 ? P : 1), 256>>>(anchor, pos, out, P);

    // 148 SMs x 8 blocks of 256 threads = full occupancy, one wave
    const int grid = 148 * 8;
    loss_kernel<<<grid, 256>>>(anchor, neg, out, num_full, P);
}

// round 3
// speedup vs baseline: 1.9878x; 1.9878x over previous
#include <cuda_runtime.h>
#include <math.h>

// Triplet-margin ranking loss, GB300 sm_103a — single fused streaming kernel.
// anchor: (1, 2400) f32, positive: (P=5, 2400) f32, negative: (N=100000, 2400) f32
// loss = sum_{i<num_full} relu(d_ap[i % P] - d_an[i] + MARGIN)
// d_x = || anchor - x + EPS ||_2  (elementwise +EPS, torch pairwise_distance)

#define EPS    1e-6f
#define MARGIN 1.0f
#define DIM    2400
#define DIM4   (DIM / 4)   // 600 float4 per row

// ---------------------------------------------------------------------------
// Fused kernel: every block
//   1. stages anchor into shared (9.6 KB)
//   2. computes d_ap[0..P-1] inline (warp w reduces positive row w; pos is
//      48 KB -> L2-resident after the first wave, ~free)
//   3. streams negative rows warp-per-row with STATIC grid-stride (dynamic
//      atomic tickets regressed 2x in R2 -- single-address atomic serializes)
//   4. block-reduces and does ONE atomicAdd to the scalar.
// d_out is zeroed by a cudaMemsetAsync node before this kernel.
// ---------------------------------------------------------------------------
__global__ void __launch_bounds__(256, 8)
loss_kernel(const float* __restrict__ anchor,
            const float* __restrict__ pos,
            const float* __restrict__ neg,
            float* __restrict__ out,
            int num_full, int P)
{
    __shared__ float4 sA[DIM4];        // anchor, 9600 B
    __shared__ float  sDap[8];
    __shared__ float  sWarp[8];

    const int wid  = threadIdx.x >> 5;
    const int lane = threadIdx.x & 31;

    // ---- stage anchor ----
    const float4* a4 = reinterpret_cast<const float4*>(anchor);
    for (int k = threadIdx.x; k < DIM4; k += blockDim.x)
        sA[k] = a4[k];

    // ---- inline d_ap: warp w handles positive row w (w < P <= 8) ----
    if (wid < P) {
        const float4* p4 = reinterpret_cast<const float4*>(pos + (size_t)wid * DIM);
        float s = 0.0f;
        #pragma unroll 4
        for (int k = lane; k < DIM4; k += 32) {
            float4 a = a4[k];          // anchor straight from L1/L2 (smem not synced yet)
            float4 p = __ldg(&p4[k]);
            float d0 = a.x - p.x + EPS;
            float d1 = a.y - p.y + EPS;
            float d2 = a.z - p.z + EPS;
            float d3 = a.w - p.w + EPS;
            s = fmaf(d0, d0, s);
            s = fmaf(d1, d1, s);
            s = fmaf(d2, d2, s);
            s = fmaf(d3, d3, s);
        }
        #pragma unroll
        for (int o = 16; o > 0; o >>= 1)
            s += __shfl_xor_sync(0xFFFFFFFFu, s, o);
        if (lane == 0) sDap[wid] = sqrtf(s);
    }
    __syncthreads();

    // ---- static warp-per-row grid-stride over negatives ----
    const int nwarps = blockDim.x >> 5;
    const int gwarp  = blockIdx.x * nwarps + wid;
    const int W      = gridDim.x * nwarps;

    float acc = 0.0f;

    for (int row = gwarp; row < num_full; row += W) {
        const float4* n4 = reinterpret_cast<const float4*>(neg + (size_t)row * DIM);
        float s = 0.0f;
        // 600 float4 / 32 lanes = 18.75 iterations; unroll for MLP
        #pragma unroll 4
        for (int k = lane; k < DIM4; k += 32) {
            float4 a = sA[k];
            float4 n = __ldg(&n4[k]);
            float d0 = a.x - n.x + EPS;
            float d1 = a.y - n.y + EPS;
            float d2 = a.z - n.z + EPS;
            float d3 = a.w - n.w + EPS;
            s = fmaf(d0, d0, s);
            s = fmaf(d1, d1, s);
            s = fmaf(d2, d2, s);
            s = fmaf(d3, d3, s);
        }
        #pragma unroll
        for (int o = 16; o > 0; o >>= 1)
            s += __shfl_xor_sync(0xFFFFFFFFu, s, o);
        if (lane == 0) {
            float d_an = sqrtf(s);
            float t = sDap[row % P] - d_an + MARGIN;
            acc += (t > 0.0f) ? t : 0.0f;
        }
    }

    // ---- block reduction + single atomic ----
    if (lane == 0) sWarp[wid] = acc;
    __syncthreads();
    if (threadIdx.x == 0) {
        float bsum = 0.0f;
        #pragma unroll
        for (int i = 0; i < 8; i++) bsum += sWarp[i];
        atomicAdd(out, bsum);
    }
}

// ---------------------------------------------------------------------------
extern "C" void kernel_launch(void* const* d_in, const int* in_sizes, int n_in,
                              void* d_out, int out_size)
{
    const float* anchor = (const float*)d_in[0];
    const float* pos    = (const float*)d_in[1];
    const float* neg    = (const float*)d_in[2];
    float* out = (float*)d_out;

    const int P = in_sizes[1] / DIM;          // 5
    const int N = in_sizes[2] / DIM;          // 100000
    const int num_full = (N / P) * P;         // 100000

    // zero the poisoned output scalar (async memset is graph-capturable)
    cudaMemsetAsync(d_out, 0, sizeof(float));

    // 148 SMs x 8 blocks of 256 threads = full occupancy, one wave
    const int grid = 148 * 8;
    loss_kernel<<<grid, 256>>>(anchor, pos, neg, out, num_full, P);
}